// round 6
// baseline (speedup 1.0000x reference)
#include <cuda_runtime.h>
#include <cstdint>

#define BB 16
#define HH 512
#define WW 512
#define HW (HH*WW)
#define SEGY 16            // output rows per block
#define TR (SEGY + 30)     // 46 tile rows (15 halo each side)

// Scratch (no allocations allowed -> __device__ globals)
__device__ float        g_part[BB*HH*4];   // per-(b,row) partial sums
__device__ float        g_lossb[BB];       // per-batch loss
__device__ unsigned int g_count;           // completion counter (zero-init, self-reset)

// ---------------------------------------------------------------------------
// Fused kernel: mask tile -> vertical 31-sum (smem) -> per-row horizontal
// window via register/shuffle prefix -> fused log-softmax CE + wIoU terms
// -> per-row partials. No global intermediate.
// Grid: (B, 32 y-bands of 16 rows), 512 threads (16 warps; warp w = row y0+w).
__global__ __launch_bounds__(512, 2)
void fused_kernel(const float* __restrict__ pred, const int* __restrict__ mask32) {
    const int tid = threadIdx.x;
    const int b   = blockIdx.x;
    const int y0  = blockIdx.y * SEGY;

    __shared__ unsigned char  tile[TR][WW];     // mask halo tile (u8)
    __shared__ unsigned short csum[SEGY][WW];   // vertical 31-sums (u16)
    __shared__ int sflag;

    // --- dtype detection: int64 non-negative => all odd 32-bit words are 0 ---
    if (tid == 0) sflag = 0;
    __syncthreads();
    if (tid < 64) {
        int v = mask32[2 * tid + 1];
        if (v != 0) atomicOr(&sflag, 1);
    }
    __syncthreads();
    const bool is64 = (sflag == 0);

    // --- cooperative tile load: row r = global row y0-15+r (zeros outside) ---
    if (is64) {
        const int* mb = mask32 + ((size_t)b * HW) * 2;
        #pragma unroll 4
        for (int r = 0; r < TR; ++r) {
            const int y = y0 - 15 + r;
            unsigned char u = 0;
            if ((unsigned)y < (unsigned)HH)
                u = (unsigned char)(__ldg(mb + (((size_t)y * WW + tid) << 1)) == 1);
            tile[r][tid] = u;
        }
    } else {
        const int* mb = mask32 + (size_t)b * HW;
        #pragma unroll 4
        for (int r = 0; r < TR; ++r) {
            const int y = y0 - 15 + r;
            unsigned char u = 0;
            if ((unsigned)y < (unsigned)HH)
                u = (unsigned char)(__ldg(mb + (size_t)y * WW + tid) == 1);
            tile[r][tid] = u;
        }
    }
    __syncthreads();

    // --- phase 1: vertical sliding 31-sum, one column per thread ---
    {
        int sum = 0;
        #pragma unroll
        for (int r = 0; r < 31; ++r) sum += (int)tile[r][tid];
        #pragma unroll
        for (int i = 0; i < SEGY; ++i) {
            csum[i][tid] = (unsigned short)sum;
            if (i < SEGY - 1)
                sum += (int)tile[31 + i][tid] - (int)tile[i][tid];
        }
    }
    __syncthreads();

    // --- phase 2: warp w handles row y = y0 + w ---
    const int lane = tid & 31;
    const int w    = tid >> 5;
    const int y    = y0 + w;

    // colsum row: 16 u16 per thread (contiguous 32B -> conflict-free LDS.128)
    uint4 cs0 = ((const uint4*)&csum[w][0])[lane * 2];
    uint4 cs1 = ((const uint4*)&csum[w][0])[lane * 2 + 1];
    // mask row bytes: 16 u8 per thread (contiguous 16B)
    uint4 mword = ((const uint4*)&tile[15 + w][0])[lane];
    const unsigned char* mbytes = (const unsigned char*)&mword;

    // thread-local inclusive prefix of the 16 colsums
    int pre[16];
    {
        const unsigned* c0 = (const unsigned*)&cs0;
        const unsigned* c1 = (const unsigned*)&cs1;
        int run = 0;
        #pragma unroll
        for (int j = 0; j < 16; ++j) {
            unsigned word = (j < 8) ? c0[j >> 1] : c1[(j - 8) >> 1];
            run += (int)((word >> ((j & 1) * 16)) & 0xffffu);
            pre[j] = run;
        }
    }
    // warp scan of thread totals -> exclusive base, inclusive global prefix
    int tot = pre[15], v = tot;
    #pragma unroll
    for (int o = 1; o < 32; o <<= 1) {
        int n = __shfl_up_sync(0xffffffffu, v, o);
        if (lane >= o) v += n;
    }
    const int base = v - tot;
    int inc[16];
    #pragma unroll
    for (int j = 0; j < 16; ++j) inc[j] = base + pre[j];

    // --- fused per-pixel loss, pred loaded in 2 chunks to limit registers ---
    const float* p0base = pred + ((size_t)(2 * b)    ) * HW + (size_t)y * WW;
    const float* p1base = pred + ((size_t)(2 * b) + 1) * HW + (size_t)y * WW;

    float a0 = 0.f, a1 = 0.f, a2 = 0.f, a3 = 0.f;
    #pragma unroll
    for (int c = 0; c < 2; ++c) {
        float4 q0[2], q1[2];
        q0[0] = ((const float4*)p0base)[lane * 4 + c * 2];
        q0[1] = ((const float4*)p0base)[lane * 4 + c * 2 + 1];
        q1[0] = ((const float4*)p1base)[lane * 4 + c * 2];
        q1[1] = ((const float4*)p1base)[lane * 4 + c * 2 + 1];
        const float* f0 = (const float*)q0;
        const float* f1 = (const float*)q1;

        #pragma unroll
        for (int jj = 0; jj < 8; ++jj) {
            const int j = c * 8 + jj;
            // P[x+15]: own inc[15] at j==0; else lane+1's inc[j-1] (lane31 -> own inc[15])
            int Ph;
            if (j == 0) {
                Ph = inc[15];
            } else {
                int s = __shfl_down_sync(0xffffffffu, inc[j - 1], 1);
                Ph = (lane == 31) ? inc[15] : s;
            }
            // P[x-16]: lane-1's inc[j] (lane0 -> 0)
            int t = __shfl_up_sync(0xffffffffu, inc[j], 1);
            int Pl = (lane == 0) ? 0 : t;

            float pooled = (float)(Ph - Pl) * (1.0f / 961.0f);

            unsigned m = mbytes[j];
            float mf = (float)m;

            float d = f1[jj] - f0[jj];
            float a = fabsf(d);
            float e = __expf(-a);
            float l = __logf(1.0f + e);
            bool dpos = (d >= 0.f);

            float wbce   = l + ((dpos == (m != 0u)) ? 0.f : a);
            float p1prob = __fdividef(dpos ? 1.0f : e, 1.0f + e);
            float weit   = 1.0f + 5.0f * fabsf(pooled - mf);

            a0 += weit;
            a1 += weit * wbce;
            a2 += p1prob * mf * weit;
            a3 += (p1prob + mf) * weit;
        }
    }

    // --- warp reduce & write row partials ---
    #pragma unroll
    for (int o = 16; o > 0; o >>= 1) {
        a0 += __shfl_down_sync(0xffffffffu, a0, o);
        a1 += __shfl_down_sync(0xffffffffu, a1, o);
        a2 += __shfl_down_sync(0xffffffffu, a2, o);
        a3 += __shfl_down_sync(0xffffffffu, a3, o);
    }
    if (lane == 0) {
        float* out = g_part + ((size_t)b * HH + y) * 4;
        out[0] = a0; out[1] = a1; out[2] = a2; out[3] = a3;
    }
}

// ---------------------------------------------------------------------------
// Pass 3: 16 blocks, block b reduces batch b's 512 row-partials (float4,
// coalesced), computes batch loss; last block (fenced atomic counter)
// averages the 16 losses, writes out[0], resets the counter (replay-safe).
__global__ void pass3_kernel(float* __restrict__ out) {
    const int b   = blockIdx.x;
    const int tid = threadIdx.x;          // 128 threads
    const int lane = tid & 31, warp = tid >> 5;

    const float4* p = (const float4*)g_part + (size_t)b * HH;
    float s0 = 0.f, s1 = 0.f, s2 = 0.f, s3 = 0.f;
    #pragma unroll
    for (int i = tid; i < HH; i += 128) {
        float4 v = p[i];
        s0 += v.x; s1 += v.y; s2 += v.z; s3 += v.w;
    }
    #pragma unroll
    for (int o = 16; o > 0; o >>= 1) {
        s0 += __shfl_down_sync(0xffffffffu, s0, o);
        s1 += __shfl_down_sync(0xffffffffu, s1, o);
        s2 += __shfl_down_sync(0xffffffffu, s2, o);
        s3 += __shfl_down_sync(0xffffffffu, s3, o);
    }
    __shared__ float red[4][4];
    if (lane == 0) { red[warp][0] = s0; red[warp][1] = s1; red[warp][2] = s2; red[warp][3] = s3; }
    __syncthreads();
    if (tid == 0) {
        float r0 = red[0][0] + red[1][0] + red[2][0] + red[3][0];
        float r1 = red[0][1] + red[1][1] + red[2][1] + red[3][1];
        float r2 = red[0][2] + red[1][2] + red[2][2] + red[3][2];
        float r3 = red[0][3] + red[1][3] + red[2][3] + red[3][3];

        float wbce  = r1 / r0;
        float inter = r2;
        float uni   = r3 - r2;                     // cardinality - inter
        float wiou  = 1.f - (inter + 1.f) / (uni + 1.f);
        g_lossb[b] = wbce + wiou;

        __threadfence();
        unsigned int old = atomicAdd(&g_count, 1u);
        if (old == (BB - 1)) {
            __threadfence();
            volatile float* lb = g_lossb;
            float t = 0.f;
            #pragma unroll
            for (int i = 0; i < BB; ++i) t += lb[i];
            out[0] = t * (1.f / (float)BB);
            atomicExch(&g_count, 0u);              // reset for next graph replay
        }
    }
}

// ---------------------------------------------------------------------------
extern "C" void kernel_launch(void* const* d_in, const int* in_sizes, int n_in,
                              void* d_out, int out_size) {
    const float* pred   = (const float*)d_in[0];
    const int*   mask32 = (const int*)d_in[1];   // 32-bit view; dtype detected in-kernel
    float* out = (float*)d_out;

    fused_kernel<<<dim3(BB, 32), 512>>>(pred, mask32);
    pass3_kernel<<<BB, 128>>>(out);
}